// round 1
// baseline (speedup 1.0000x reference)
#include <cuda_runtime.h>

// ---------------- problem constants ----------------
// x: (2, 4, 32, 128, 128) f32; W_conv: (4,3,3,1,8); W_pos: (4,16,8);
// W_app: (4,16,8); b_app: (4,8). out: (2, 8, 32, 128, 128) f32.

#define TH 4
#define TW 8
#define PS 61              // padded plane stride for 6x10 region (60 -> 61, odd)
#define CS (32*PS + 4)     // per-t0 stride in xs = 1956 (extra +4 for c-bank offset)
#define XS_FLOATS (4*CS)   // 7824
#define VT 33              // v stage: stride over t (8 t's padded to 33 per t slot)
#define VPX (8*VT)         // 264 per pixel
#define VWARP (8*VPX)      // 2112 per warp (8 pixels)
#define SMEM_FLOATS (XS_FLOATS + 4*VWARP)
#define SMEM_BYTES (SMEM_FLOATS * 4)

__global__ __launch_bounds__(128, 3)
void caps2d_matwo_kernel(const float* __restrict__ x,
                         const float* __restrict__ Wc,
                         const float* __restrict__ Wp,
                         const float* __restrict__ Wa,
                         const float* __restrict__ ba,
                         float* __restrict__ out)
{
    extern __shared__ float smem[];
    float* xs = smem;              // x tile: [c=4][z=32][6][10] padded
    float* vs = smem + XS_FLOATS;  // v staging: [warp=4][px=8][t=8(+pad)][z=32]

    const int tid  = threadIdx.x;
    const int wid  = tid >> 5;     // warp = tile row (0..3)
    const int lane = tid & 31;
    const int n    = blockIdx.z;
    const int w0   = blockIdx.x * TW;
    const int h0   = blockIdx.y * TH;

    // lane -> capsule (c = t0, t = t1_out)
    const int c  = lane >> 3;
    const int t  = lane & 7;
    const int ca = t >> 1;          // conv channel for pos part
    const int zr = (t & 1) << 4;    // z base (0 or 16)

    // ---- per-lane constants (conv taps, transform matrices) ----
    float wka[9], wkb[9];
#pragma unroll
    for (int i = 0; i < 9; i++) {
        wka[i] = Wc[(c*9 + i)*8 + ca];       // channel t//2
        wkb[i] = Wc[(c*9 + i)*8 + 4 + ca];   // channel 4 + t//2
    }
    float Mp[4][4], Ma[4][4];
#pragma unroll
    for (int j = 0; j < 4; j++)
#pragma unroll
        for (int k = 0; k < 4; k++) {
            Mp[j][k] = Wp[c*128 + t*16 + j*4 + k];
            Ma[j][k] = Wa[c*128 + t*16 + j*4 + k];
        }
    // column-normalize Mp (reference: / sqrt(max(sum_j m^2, 1e-12)))
#pragma unroll
    for (int k = 0; k < 4; k++) {
        float s = Mp[0][k]*Mp[0][k] + Mp[1][k]*Mp[1][k]
                + Mp[2][k]*Mp[2][k] + Mp[3][k]*Mp[3][k];
        float inv = rsqrtf(fmaxf(s, 1e-12f));
#pragma unroll
        for (int j = 0; j < 4; j++) Mp[j][k] *= inv;
    }
    const float bias = ba[c*8 + t];
    float bcol[4];   // bias * column sums of Ma (folds the bias add into the matmul)
#pragma unroll
    for (int k = 0; k < 4; k++)
        bcol[k] = bias * (Ma[0][k] + Ma[1][k] + Ma[2][k] + Ma[3][k]);

    // ---- cooperative load of the x tile (with 3x3 halo, zero padded) ----
    {
        const float* xin = x + (size_t)n * (128 * 16384);
        for (int idx = tid; idx < 128*60; idx += 128) {
            int p   = idx / 60;            // plane = c*32 + z
            int rem = idx - p*60;
            int yy  = rem / 10;
            int xx  = rem - yy*10;
            int gh  = h0 - 1 + yy;
            int gw  = w0 - 1 + xx;
            float v = 0.f;
            if ((unsigned)gh < 128u && (unsigned)gw < 128u)
                v = xin[p*16384 + gh*128 + gw];
            xs[(p >> 5)*CS + (p & 31)*PS + rem] = v;
        }
    }
    __syncthreads();

    const float* xb = xs + c*CS + zr*PS + wid*10;   // lane's conv base for this row
    float* vsw = vs + wid*VWARP;
    const float cy = (float)(h0 + wid) * (1.0f/128.0f);

    for (int px = 0; px < TW; px++) {
        // ---- 3x3 conv: 16 z-planes x 2 output channels per lane (exact, no redundancy)
        float up[16], ua[16];
#pragma unroll
        for (int zp = 0; zp < 16; zp++) {
            const float* zb = xb + zp*PS + px;
            float aa = 0.f, ab = 0.f;
#pragma unroll
            for (int dy = 0; dy < 3; dy++)
#pragma unroll
                for (int dx = 0; dx < 3; dx++) {
                    float xv = zb[dy*10 + dx];
                    aa += xv * wka[dy*3 + dx];
                    ab += xv * wkb[dy*3 + dx];
                }
            up[zp] = aa;
            ua[zp] = ab;
        }

        // ---- capsule transforms: u_hat[32] per lane ----
        const float cx = (float)(w0 + px) * (1.0f/128.0f);
        float uh[32];
#pragma unroll
        for (int i = 0; i < 4; i++) {
            float u0 = up[i*4+0], u1 = up[i*4+1], u2 = up[i*4+2], u3 = up[i*4+3];
#pragma unroll
            for (int k = 0; k < 4; k++)
                uh[i*4+k] = u0*Mp[0][k] + u1*Mp[1][k] + u2*Mp[2][k] + u3*Mp[3][k];
            uh[i*4+0] += u3 * cx;   // coord row (j==3, k==0): w/128
            uh[i*4+1] += u3 * cy;   // coord row (j==3, k==1): h/128
            float a0 = ua[i*4+0], a1 = ua[i*4+1], a2 = ua[i*4+2], a3 = ua[i*4+3];
#pragma unroll
            for (int k = 0; k < 4; k++)
                uh[16+i*4+k] = a0*Ma[0][k] + a1*Ma[1][k] + a2*Ma[2][k] + a3*Ma[3][k]
                             + bcol[k];
        }

        // ---- dynamic routing (3 passes), fully warp-local ----
        float p[32];
        float bb = 0.f;
        float inv_pos = 0.f, fapp = 0.f;
#pragma unroll
        for (int it = 0; it < 3; it++) {
            float r = __fdividef(1.f, 1.f + __expf(-bb));   // sigmoid(b[c,t])
            // p[z,t] = sum_c uh[z,c,t]*r[c,t] : butterfly over the 4 c-lanes
#pragma unroll
            for (int z = 0; z < 32; z++) {
                float pr = uh[z] * r;
                pr += __shfl_xor_sync(0xffffffffu, pr, 8);
                pr += __shfl_xor_sync(0xffffffffu, pr, 16);
                p[z] = pr;
            }
            float m = 0.f;
#pragma unroll
            for (int z = 0; z < 16; z++) m = fmaxf(m, fabsf(p[z]));
            float sq = 0.f;
#pragma unroll
            for (int z = 16; z < 32; z++) sq += p[z]*p[z];
            inv_pos = __fdividef(1.f, m);                         // psquash scale
            fapp = __fdividef(sq, 1.f + sq) * rsqrtf(sq + 1e-9f); // matwo scale
            if (it < 2) {
                float dp = 0.f, da = 0.f;
#pragma unroll
                for (int z = 0;  z < 16; z++) dp += uh[z]*p[z];
#pragma unroll
                for (int z = 16; z < 32; z++) da += uh[z]*p[z];
                bb += (dp * inv_pos) * (da * fapp);   // rout[c,t]
            }
        }
        // stage v for this pixel; lane (c,t) owns z in [c*8, c*8+8)
#pragma unroll
        for (int zi = 0; zi < 8; zi++) {
            int z = c*8 + zi;
            float sc = (z < 16) ? inv_pos : fapp;
            vsw[px*VPX + t*VT + z] = p[z] * sc;
        }
    }

    __syncwarp();

    // ---- coalesced output: lane = z, float4 x2 per (t, row) ----
    const int hout = h0 + wid;
#pragma unroll
    for (int tt = 0; tt < 8; tt++) {
        float a[8];
#pragma unroll
        for (int px = 0; px < 8; px++)
            a[px] = vsw[px*VPX + tt*VT + lane];
        size_t base = ((size_t)((n*8 + tt)*32 + lane))*16384 + (size_t)hout*128 + w0;
        float4* o4 = reinterpret_cast<float4*>(out + base);
        o4[0] = make_float4(a[0], a[1], a[2], a[3]);
        o4[1] = make_float4(a[4], a[5], a[6], a[7]);
    }
}

extern "C" void kernel_launch(void* const* d_in, const int* in_sizes, int n_in,
                              void* d_out, int out_size)
{
    const float* x  = (const float*)d_in[0];
    const float* Wc = (const float*)d_in[1];
    const float* Wp = (const float*)d_in[2];
    const float* Wa = (const float*)d_in[3];
    const float* ba = (const float*)d_in[4];
    float* out = (float*)d_out;

    cudaFuncSetAttribute(caps2d_matwo_kernel,
                         cudaFuncAttributeMaxDynamicSharedMemorySize, SMEM_BYTES);

    dim3 grid(128/TW, 128/TH, 2);   // 16 x 32 x 2 = 1024 blocks
    caps2d_matwo_kernel<<<grid, 128, SMEM_BYTES>>>(x, Wc, Wp, Wa, ba, out);
}

// round 7
// speedup vs baseline: 1.2375x; 1.2375x over previous
#include <cuda_runtime.h>

// x: (2,4,32,128,128) f32; W_conv: (4,3,3,1,8); W_pos: (4,16,8);
// W_app: (4,16,8); b_app: (4,8). out: (2,8,32,128,128) f32.

#define TH 4
#define TW 8
// xs quad layout: [c][quad=8][row=6][col=10][4z]
#define RS 244                 // per-quad stride (240 + 4), RS % 8 == 4 -> conflict-free groups
#define CS 1952                // 8*RS
#define XS_FLOATS (4*CS)       // 7808
// M staging: [c][s=2][t=8][j=4][k=4] with per-t stride 20 (conflict-tuned)
#define MS_OFF   XS_FLOATS
#define MS_FLOATS (4*2*8*20)   // 1280
#define BC_OFF   (MS_OFF + MS_FLOATS)
#define BC_FLOATS 128          // [c][t][4]
// v staging (half tile: 4 px), per warp [px=4][t=8][36]
#define VT 36
#define VPX (8*VT)             // 288
#define VWARP (4*VPX)          // 1152
#define VS_OFF   (BC_OFF + BC_FLOATS)
#define SMEM_FLOATS (VS_OFF + 4*VWARP)   // 13824
#define SMEM_BYTES  (SMEM_FLOATS*4)      // 55296

__device__ __forceinline__ float bflyMax(float v) {
    v = fmaxf(v, __shfl_xor_sync(0xffffffffu, v, 8));
    v = fmaxf(v, __shfl_xor_sync(0xffffffffu, v, 16));
    return v;
}
__device__ __forceinline__ float bflySum(float v) {
    v += __shfl_xor_sync(0xffffffffu, v, 8);
    v += __shfl_xor_sync(0xffffffffu, v, 16);
    return v;
}

__global__ __launch_bounds__(128, 4)
void caps2d_matwo_kernel(const float* __restrict__ x,
                         const float* __restrict__ Wc,
                         const float* __restrict__ Wp,
                         const float* __restrict__ Wa,
                         const float* __restrict__ ba,
                         float* __restrict__ out)
{
    extern __shared__ float smem[];
    float* xs  = smem;
    float* MS  = smem + MS_OFF;
    float* bcS = smem + BC_OFF;
    float* vs  = smem + VS_OFF;

    const int tid  = threadIdx.x;
    const int wid  = tid >> 5;
    const int lane = tid & 31;
    const int n    = blockIdx.z;
    const int w0   = blockIdx.x * TW;
    const int h0   = blockIdx.y * TH;

    // lane -> (q, t): q owns z in [8q, 8q+8); q<2 pos, q>=2 app
    const int q   = lane >> 3;
    const int t   = lane & 7;
    const int tb  = t & 1;
    const int ca  = t >> 1;
    const int qp  = q & 1;
    const int isApp = q >> 1;
    const int ch  = ca + isApp * 4;

    // ---- one-time per-block: normalized Mp, raw Ma, bias*colsum into shared ----
    if (tid < 32) {
        int c = tid >> 3, tt = tid & 7;
        float M[16];
#pragma unroll
        for (int i = 0; i < 16; i++) M[i] = Wp[c*128 + tt*16 + i];
#pragma unroll
        for (int k = 0; k < 4; k++) {
            float s = M[k]*M[k] + M[4+k]*M[4+k] + M[8+k]*M[8+k] + M[12+k]*M[12+k];
            float inv = rsqrtf(fmaxf(s, 1e-12f));
#pragma unroll
            for (int j = 0; j < 4; j++) M[j*4+k] *= inv;
        }
        float* mp = MS + ((c*2 + 0)*8 + tt)*20;
#pragma unroll
        for (int i = 0; i < 16; i++) mp[i] = M[i];
        float A[16];
#pragma unroll
        for (int i = 0; i < 16; i++) A[i] = Wa[c*128 + tt*16 + i];
        float* mpa = MS + ((c*2 + 1)*8 + tt)*20;
#pragma unroll
        for (int i = 0; i < 16; i++) mpa[i] = A[i];
        float bias = ba[c*8 + tt];
#pragma unroll
        for (int k = 0; k < 4; k++)
            bcS[(c*8 + tt)*4 + k] = bias * (A[k] + A[4+k] + A[8+k] + A[12+k]);
    }

    // ---- conv weights per lane: w[c][tap] for its single channel ----
    float wk[36];
#pragma unroll
    for (int c = 0; c < 4; c++)
#pragma unroll
        for (int i = 0; i < 9; i++)
            wk[c*9 + i] = Wc[(c*9 + i)*8 + ch];

    // ---- tile load: x[n, plane, h, w] -> z-quad interleaved shared ----
    {
        const float* xin = x + (size_t)n * (128 * 16384);
        for (int idx = tid; idx < 1920; idx += 128) {
            int col = idx % 10;
            int tmp = idx / 10;
            int r   = tmp % 6;
            int pq  = tmp / 6;                // 0..31 (c*8 + quad)
            int gh  = h0 - 1 + r;
            int gw  = w0 - 1 + col;
            float4 v = make_float4(0.f, 0.f, 0.f, 0.f);
            if ((unsigned)gh < 128u && (unsigned)gw < 128u) {
                const float* gp = xin + (size_t)(pq*4)*16384 + gh*128 + gw;
                v.x = gp[0]; v.y = gp[16384]; v.z = gp[32768]; v.w = gp[49152];
            }
            *reinterpret_cast<float4*>(xs + (pq >> 3)*CS + (pq & 7)*RS + r*40 + col*4) = v;
        }
    }
    __syncthreads();

    const float cy = (float)(h0 + wid) * (1.0f/128.0f);
    const int   hout = h0 + wid;
    // lane's quad base within xs (c added in loop): quadIdx = 4*tb + 2*qp + kq
    const float* xbase = xs + (4*tb + 2*qp)*RS + wid*40;
    float* vsw = vs + wid*VWARP;

    for (int ph = 0; ph < 2; ph++) {
#pragma unroll 1
        for (int pxl = 0; pxl < 4; pxl++) {
            const int px = ph*4 + pxl;
            const float cx = (float)(w0 + px) * (1.0f/128.0f);

            // ---- conv + transform: uh[c][zl] for all 4 c, own 8 z-rows ----
            float uh0[8], uh1[8], uh2[8], uh3[8];
#pragma unroll
            for (int c = 0; c < 4; c++) {
                float u[8];
#pragma unroll
                for (int i = 0; i < 8; i++) u[i] = 0.f;
#pragma unroll
                for (int kq = 0; kq < 2; kq++) {
                    const float* bptr = xbase + c*CS + kq*RS + px*4;
#pragma unroll
                    for (int dy = 0; dy < 3; dy++)
#pragma unroll
                        for (int dx = 0; dx < 3; dx++) {
                            float4 xv = *reinterpret_cast<const float4*>(bptr + dy*40 + dx*4);
                            float wt = wk[c*9 + dy*3 + dx];
                            u[kq*4+0] = fmaf(xv.x, wt, u[kq*4+0]);
                            u[kq*4+1] = fmaf(xv.y, wt, u[kq*4+1]);
                            u[kq*4+2] = fmaf(xv.z, wt, u[kq*4+2]);
                            u[kq*4+3] = fmaf(xv.w, wt, u[kq*4+3]);
                        }
                }
                const float* Mb = MS + ((c*2 + isApp)*8 + t)*20;
                float4 M0 = *reinterpret_cast<const float4*>(Mb);
                float4 M1 = *reinterpret_cast<const float4*>(Mb + 4);
                float4 M2 = *reinterpret_cast<const float4*>(Mb + 8);
                float4 M3 = *reinterpret_cast<const float4*>(Mb + 12);
                float4 bc = make_float4(0.f, 0.f, 0.f, 0.f);
                if (isApp) bc = *reinterpret_cast<const float4*>(bcS + (c*8 + t)*4);
                float4 a0 = bc, a1 = bc;
                a0.x = fmaf(u[0],M0.x, fmaf(u[1],M1.x, fmaf(u[2],M2.x, fmaf(u[3],M3.x, a0.x))));
                a0.y = fmaf(u[0],M0.y, fmaf(u[1],M1.y, fmaf(u[2],M2.y, fmaf(u[3],M3.y, a0.y))));
                a0.z = fmaf(u[0],M0.z, fmaf(u[1],M1.z, fmaf(u[2],M2.z, fmaf(u[3],M3.z, a0.z))));
                a0.w = fmaf(u[0],M0.w, fmaf(u[1],M1.w, fmaf(u[2],M2.w, fmaf(u[3],M3.w, a0.w))));
                a1.x = fmaf(u[4],M0.x, fmaf(u[5],M1.x, fmaf(u[6],M2.x, fmaf(u[7],M3.x, a1.x))));
                a1.y = fmaf(u[4],M0.y, fmaf(u[5],M1.y, fmaf(u[6],M2.y, fmaf(u[7],M3.y, a1.y))));
                a1.z = fmaf(u[4],M0.z, fmaf(u[5],M1.z, fmaf(u[6],M2.z, fmaf(u[7],M3.z, a1.z))));
                a1.w = fmaf(u[4],M0.w, fmaf(u[5],M1.w, fmaf(u[6],M2.w, fmaf(u[7],M3.w, a1.w))));
                if (!isApp) {   // coordinate addend (pos only): += u3*cx (k=0), u3*cy (k=1)
                    a0.x = fmaf(u[3], cx, a0.x);  a0.y = fmaf(u[3], cy, a0.y);
                    a1.x = fmaf(u[7], cx, a1.x);  a1.y = fmaf(u[7], cy, a1.y);
                }
                float* dst = (c==0)?uh0:(c==1)?uh1:(c==2)?uh2:uh3;
                dst[0]=a0.x; dst[1]=a0.y; dst[2]=a0.z; dst[3]=a0.w;
                dst[4]=a1.x; dst[5]=a1.y; dst[6]=a1.z; dst[7]=a1.w;
            }

            // ---- routing: every lane tracks all 4 b_c; p is lane-local ----
            float b0=0.f, b1=0.f, b2=0.f, b3=0.f;
            float pz[8];
            float invpos = 0.f, fapp = 0.f;
#pragma unroll
            for (int it = 0; it < 3; it++) {
                float r0 = __fdividef(1.f, 1.f + __expf(-b0));
                float r1 = __fdividef(1.f, 1.f + __expf(-b1));
                float r2 = __fdividef(1.f, 1.f + __expf(-b2));
                float r3 = __fdividef(1.f, 1.f + __expf(-b3));
#pragma unroll
                for (int z = 0; z < 8; z++)
                    pz[z] = fmaf(uh0[z],r0, fmaf(uh1[z],r1, fmaf(uh2[z],r2, uh3[z]*r3)));
                float mm = 0.f, sq = 0.f;
                if (!isApp) {
#pragma unroll
                    for (int z = 0; z < 8; z++) mm = fmaxf(mm, fabsf(pz[z]));
                } else {
#pragma unroll
                    for (int z = 0; z < 8; z++) sq = fmaf(pz[z], pz[z], sq);
                }
                mm = bflyMax(mm);
                sq = bflySum(sq);
                invpos = __fdividef(1.f, mm);
                fapp   = __fdividef(sq, 1.f + sq) * rsqrtf(sq + 1e-9f);
                if (it < 2) {
                    float d0=0.f, d1=0.f, d2=0.f, d3=0.f;
#pragma unroll
                    for (int z = 0; z < 8; z++) {
                        d0 = fmaf(uh0[z], pz[z], d0);
                        d1 = fmaf(uh1[z], pz[z], d1);
                        d2 = fmaf(uh2[z], pz[z], d2);
                        d3 = fmaf(uh3[z], pz[z], d3);
                    }
                    float z0 = isApp ? 0.f : d0, y0 = isApp ? d0 : 0.f;
                    float z1 = isApp ? 0.f : d1, y1 = isApp ? d1 : 0.f;
                    float z2 = isApp ? 0.f : d2, y2 = isApp ? d2 : 0.f;
                    float z3 = isApp ? 0.f : d3, y3 = isApp ? d3 : 0.f;
                    z0 = bflySum(z0); y0 = bflySum(y0);
                    z1 = bflySum(z1); y1 = bflySum(y1);
                    z2 = bflySum(z2); y2 = bflySum(y2);
                    z3 = bflySum(z3); y3 = bflySum(y3);
                    b0 += (z0 * invpos) * (y0 * fapp);
                    b1 += (z1 * invpos) * (y1 * fapp);
                    b2 += (z2 * invpos) * (y2 * fapp);
                    b3 += (z3 * invpos) * (y3 * fapp);
                }
            }
            // stage scaled v for own 8 z
            float sc = isApp ? fapp : invpos;
            float* vp = vsw + pxl*VPX + t*VT + q*8;
            *reinterpret_cast<float4*>(vp)     =
                make_float4(pz[0]*sc, pz[1]*sc, pz[2]*sc, pz[3]*sc);
            *reinterpret_cast<float4*>(vp + 4) =
                make_float4(pz[4]*sc, pz[5]*sc, pz[6]*sc, pz[7]*sc);
        }

        __syncwarp();
        // ---- flush 4 columns: lane = z, float4 along w ----
#pragma unroll
        for (int tt = 0; tt < 8; tt++) {
            float4 o;
            o.x = vsw[0*VPX + tt*VT + lane];
            o.y = vsw[1*VPX + tt*VT + lane];
            o.z = vsw[2*VPX + tt*VT + lane];
            o.w = vsw[3*VPX + tt*VT + lane];
            size_t base = ((size_t)((n*8 + tt)*32 + lane))*16384
                        + (size_t)hout*128 + w0 + ph*4;
            *reinterpret_cast<float4*>(out + base) = o;
        }
        __syncwarp();
    }
}

extern "C" void kernel_launch(void* const* d_in, const int* in_sizes, int n_in,
                              void* d_out, int out_size)
{
    const float* x  = (const float*)d_in[0];
    const float* Wc = (const float*)d_in[1];
    const float* Wp = (const float*)d_in[2];
    const float* Wa = (const float*)d_in[3];
    const float* ba = (const float*)d_in[4];
    float* out = (float*)d_out;

    cudaFuncSetAttribute(caps2d_matwo_kernel,
                         cudaFuncAttributeMaxDynamicSharedMemorySize, SMEM_BYTES);

    dim3 grid(128/TW, 128/TH, 2);   // 16 x 32 x 2 = 1024 blocks
    caps2d_matwo_kernel<<<grid, 128, SMEM_BYTES>>>(x, Wc, Wp, Wa, ba, out);
}

// round 8
// speedup vs baseline: 1.3244x; 1.0702x over previous
#include <cuda_runtime.h>

// x: (2,4,32,128,128) f32; W_conv: (4,3,3,1,8); W_pos: (4,16,8);
// W_app: (4,16,8); b_app: (4,8). out: (2,8,32,128,128) f32.

#define TH 4
#define TW 8
#define RS 244
#define CS 1952
#define XS_FLOATS (4*CS)
#define MS_OFF   XS_FLOATS
#define MS_FLOATS (4*2*8*20)
#define BC_OFF   (MS_OFF + MS_FLOATS)
#define BC_FLOATS 128
#define VT 36
#define VPX (8*VT)
#define VWARP (4*VPX)
#define VS_OFF   (BC_OFF + BC_FLOATS)
#define SMEM_FLOATS (VS_OFF + 4*VWARP)
#define SMEM_BYTES  (SMEM_FLOATS*4)

typedef unsigned long long u64;

__device__ __forceinline__ void ffma2(u64& acc, u64 a, u64 b) {
    asm("fma.rn.f32x2 %0, %1, %2, %0;" : "+l"(acc) : "l"(a), "l"(b));
}
__device__ __forceinline__ u64 mul2(u64 a, u64 b) {
    u64 r; asm("mul.rn.f32x2 %0, %1, %2;" : "=l"(r) : "l"(a), "l"(b)); return r;
}
__device__ __forceinline__ u64 pack2(float x, float y) {
    u64 r; asm("mov.b64 %0, {%1, %2};" : "=l"(r) : "f"(x), "f"(y)); return r;
}
__device__ __forceinline__ float2 unpack2(u64 v) {
    float2 r; asm("mov.b64 {%0, %1}, %2;" : "=f"(r.x), "=f"(r.y) : "l"(v)); return r;
}

__global__ __launch_bounds__(128, 4)
void caps2d_matwo_kernel(const float* __restrict__ x,
                         const float* __restrict__ Wc,
                         const float* __restrict__ Wp,
                         const float* __restrict__ Wa,
                         const float* __restrict__ ba,
                         float* __restrict__ out)
{
    extern __shared__ float smem[];
    float* xs  = smem;
    float* MS  = smem + MS_OFF;
    float* bcS = smem + BC_OFF;
    float* vs  = smem + VS_OFF;

    const int tid  = threadIdx.x;
    const int wid  = tid >> 5;
    const int lane = tid & 31;
    const int n    = blockIdx.z;
    const int w0   = blockIdx.x * TW;
    const int h0   = blockIdx.y * TH;

    // lane -> (q, t): q owns z in [8q, 8q+8); q<2 pos, q>=2 app
    const int q   = lane >> 3;
    const int t   = lane & 7;
    const int tb  = t & 1;
    const int ca  = t >> 1;
    const int qp  = q & 1;
    const int isApp = q >> 1;
    const int ch  = ca + isApp * 4;

    // ---- one-time per-block: normalized Mp, raw Ma, bias*colsum into shared ----
    if (tid < 32) {
        int c = tid >> 3, tt = tid & 7;
        float M[16];
#pragma unroll
        for (int i = 0; i < 16; i++) M[i] = Wp[c*128 + tt*16 + i];
#pragma unroll
        for (int k = 0; k < 4; k++) {
            float s = M[k]*M[k] + M[4+k]*M[4+k] + M[8+k]*M[8+k] + M[12+k]*M[12+k];
            float inv = rsqrtf(fmaxf(s, 1e-12f));
#pragma unroll
            for (int j = 0; j < 4; j++) M[j*4+k] *= inv;
        }
        float* mp = MS + ((c*2 + 0)*8 + tt)*20;
#pragma unroll
        for (int i = 0; i < 16; i++) mp[i] = M[i];
        float A[16];
#pragma unroll
        for (int i = 0; i < 16; i++) A[i] = Wa[c*128 + tt*16 + i];
        float* mpa = MS + ((c*2 + 1)*8 + tt)*20;
#pragma unroll
        for (int i = 0; i < 16; i++) mpa[i] = A[i];
        float bias = ba[c*8 + tt];
#pragma unroll
        for (int k = 0; k < 4; k++)
            bcS[(c*8 + tt)*4 + k] = bias * (A[k] + A[4+k] + A[8+k] + A[12+k]);
    }

    // ---- conv weights per lane ----
    float wk[36];
#pragma unroll
    for (int c = 0; c < 4; c++)
#pragma unroll
        for (int i = 0; i < 9; i++)
            wk[c*9 + i] = Wc[(c*9 + i)*8 + ch];

    // ---- tile load: x -> z-quad interleaved shared ----
    {
        const float* xin = x + (size_t)n * (128 * 16384);
        for (int idx = tid; idx < 1920; idx += 128) {
            int col = idx % 10;
            int tmp = idx / 10;
            int r   = tmp % 6;
            int pq  = tmp / 6;
            int gh  = h0 - 1 + r;
            int gw  = w0 - 1 + col;
            float4 v = make_float4(0.f, 0.f, 0.f, 0.f);
            if ((unsigned)gh < 128u && (unsigned)gw < 128u) {
                const float* gp = xin + (size_t)(pq*4)*16384 + gh*128 + gw;
                v.x = gp[0]; v.y = gp[16384]; v.z = gp[32768]; v.w = gp[49152];
            }
            *reinterpret_cast<float4*>(xs + (pq >> 3)*CS + (pq & 7)*RS + r*40 + col*4) = v;
        }
    }
    __syncthreads();

    const float cy = (float)(h0 + wid) * (1.0f/128.0f);
    const int   hout = h0 + wid;
    const float* xbase = xs + (4*tb + 2*qp)*RS + wid*40;
    float* vsw = vs + wid*VWARP;

    for (int ph = 0; ph < 2; ph++) {
#pragma unroll 1
        for (int pxl = 0; pxl < 4; pxl++) {
            const int px = ph*4 + pxl;
            const float cx = (float)(w0 + px) * (1.0f/128.0f);
            const u64 cxy = pack2(cx, cy);

            // ---- conv + transform (packed f32x2): uh pairs per c ----
            // uhX[j]: j=0 -> (z0,z1) of i-group0 cols(k0,k1); j=1 -> (k2,k3);
            //         j=2 -> i-group1 (k0,k1); j=3 -> (k2,k3)
            u64 uh0[4], uh1[4], uh2[4], uh3[4];
#pragma unroll
            for (int c = 0; c < 4; c++) {
                u64 wp[9];
#pragma unroll
                for (int i = 0; i < 9; i++) wp[i] = pack2(wk[c*9+i], wk[c*9+i]);
                u64 acc[4] = {0ull, 0ull, 0ull, 0ull};   // (z0,z1),(z2,z3) per kq
#pragma unroll
                for (int kq = 0; kq < 2; kq++) {
                    const float* bptr = xbase + c*CS + kq*RS + px*4;
#pragma unroll
                    for (int dy = 0; dy < 3; dy++)
#pragma unroll
                        for (int dx = 0; dx < 3; dx++) {
                            ulonglong2 xv = *reinterpret_cast<const ulonglong2*>(bptr + dy*40 + dx*4);
                            ffma2(acc[kq*2+0], xv.x, wp[dy*3+dx]);
                            ffma2(acc[kq*2+1], xv.y, wp[dy*3+dx]);
                        }
                }
                float2 t0 = unpack2(acc[0]), t1 = unpack2(acc[1]);
                float2 t2 = unpack2(acc[2]), t3 = unpack2(acc[3]);
                float u0 = t0.x, u1 = t0.y, u2 = t1.x, u3 = t1.y;
                float u4 = t2.x, u5 = t2.y, u6 = t3.x, u7 = t3.y;

                const float* Mb = MS + ((c*2 + isApp)*8 + t)*20;
                ulonglong2 M0 = *reinterpret_cast<const ulonglong2*>(Mb);
                ulonglong2 M1 = *reinterpret_cast<const ulonglong2*>(Mb + 4);
                ulonglong2 M2 = *reinterpret_cast<const ulonglong2*>(Mb + 8);
                ulonglong2 M3 = *reinterpret_cast<const ulonglong2*>(Mb + 12);
                u64 bc01 = 0ull, bc23 = 0ull;
                if (isApp) {
                    ulonglong2 b2 = *reinterpret_cast<const ulonglong2*>(bcS + (c*8 + t)*4);
                    bc01 = b2.x; bc23 = b2.y;
                }
                u64 a001 = bc01, a023 = bc23, a101 = bc01, a123 = bc23;
                u64 up;
                up = pack2(u0, u0); ffma2(a001, up, M0.x); ffma2(a023, up, M0.y);
                up = pack2(u1, u1); ffma2(a001, up, M1.x); ffma2(a023, up, M1.y);
                up = pack2(u2, u2); ffma2(a001, up, M2.x); ffma2(a023, up, M2.y);
                u64 u3p = pack2(u3, u3); ffma2(a001, u3p, M3.x); ffma2(a023, u3p, M3.y);
                up = pack2(u4, u4); ffma2(a101, up, M0.x); ffma2(a123, up, M0.y);
                up = pack2(u5, u5); ffma2(a101, up, M1.x); ffma2(a123, up, M1.y);
                up = pack2(u6, u6); ffma2(a101, up, M2.x); ffma2(a123, up, M2.y);
                u64 u7p = pack2(u7, u7); ffma2(a101, u7p, M3.x); ffma2(a123, u7p, M3.y);
                if (!isApp) {   // coord addend: (k0 += u3*cx, k1 += u3*cy)
                    ffma2(a001, u3p, cxy);
                    ffma2(a101, u7p, cxy);
                }
                u64* dst = (c==0)?uh0:(c==1)?uh1:(c==2)?uh2:uh3;
                dst[0]=a001; dst[1]=a023; dst[2]=a101; dst[3]=a123;
            }

            // ---- routing: lane-local p, combined-kind butterflies ----
            float b0=0.f, b1=0.f, b2=0.f, b3=0.f;
            u64 pzp[4];
            float pz[8];
            float invpos = 0.f, fapp = 0.f;
#pragma unroll
            for (int it = 0; it < 3; it++) {
                float r0 = __fdividef(1.f, 1.f + __expf(-b0));
                float r1 = __fdividef(1.f, 1.f + __expf(-b1));
                float r2 = __fdividef(1.f, 1.f + __expf(-b2));
                float r3 = __fdividef(1.f, 1.f + __expf(-b3));
                u64 rp0 = pack2(r0,r0), rp1 = pack2(r1,r1);
                u64 rp2 = pack2(r2,r2), rp3 = pack2(r3,r3);
#pragma unroll
                for (int j = 0; j < 4; j++) {
                    u64 p = 0ull;
                    ffma2(p, uh0[j], rp0); ffma2(p, uh1[j], rp1);
                    ffma2(p, uh2[j], rp2); ffma2(p, uh3[j], rp3);
                    pzp[j] = p;
                }
#pragma unroll
                for (int j = 0; j < 4; j++) {
                    float2 f = unpack2(pzp[j]);
                    pz[j*2+0] = f.x; pz[j*2+1] = f.y;
                }
                // own-kind partial: pos lanes -> max|p|, app lanes -> sum p^2
                float v;
                if (!isApp) {
                    v = 0.f;
#pragma unroll
                    for (int z = 0; z < 8; z++) v = fmaxf(v, fabsf(pz[z]));
                } else {
                    v = 0.f;
#pragma unroll
                    for (int z = 0; z < 8; z++) v = fmaf(pz[z], pz[z], v);
                }
                float o8 = __shfl_xor_sync(0xffffffffu, v, 8);
                v = isApp ? (v + o8) : fmaxf(v, o8);          // full own-kind
                float o16 = __shfl_xor_sync(0xffffffffu, v, 16);  // other kind full
                float mmF = isApp ? o16 : v;
                float sqF = isApp ? v : o16;
                invpos = __fdividef(1.f, mmF);
                fapp   = __fdividef(sqF, 1.f + sqF) * rsqrtf(sqF + 1e-9f);
                if (it < 2) {
#pragma unroll
                    for (int c = 0; c < 4; c++) {
                        const u64* uc = (c==0)?uh0:(c==1)?uh1:(c==2)?uh2:uh3;
                        u64 d = 0ull;
                        ffma2(d, uc[0], pzp[0]); ffma2(d, uc[1], pzp[1]);
                        ffma2(d, uc[2], pzp[2]); ffma2(d, uc[3], pzp[3]);
                        float2 dd = unpack2(d);
                        float s = dd.x + dd.y;                 // own-kind partial dot
                        s += __shfl_xor_sync(0xffffffffu, s, 8);     // full own-kind
                        float o = __shfl_xor_sync(0xffffffffu, s, 16); // other kind
                        float dp = isApp ? o : s;
                        float da = isApp ? s : o;
                        float rt = (dp * invpos) * (da * fapp);
                        if (c==0) b0 += rt; else if (c==1) b1 += rt;
                        else if (c==2) b2 += rt; else b3 += rt;
                    }
                }
            }
            // stage scaled v for own 8 z (packed mul + 16B stores)
            float sc = isApp ? fapp : invpos;
            u64 scp = pack2(sc, sc);
            float* vp = vsw + pxl*VPX + t*VT + q*8;
            ulonglong2 s0, s1;
            s0.x = mul2(pzp[0], scp); s0.y = mul2(pzp[1], scp);
            s1.x = mul2(pzp[2], scp); s1.y = mul2(pzp[3], scp);
            *reinterpret_cast<ulonglong2*>(vp)     = s0;
            *reinterpret_cast<ulonglong2*>(vp + 4) = s1;
        }

        __syncwarp();
        // ---- flush 4 columns: lane = z, float4 along w ----
#pragma unroll
        for (int tt = 0; tt < 8; tt++) {
            float4 o;
            o.x = vsw[0*VPX + tt*VT + lane];
            o.y = vsw[1*VPX + tt*VT + lane];
            o.z = vsw[2*VPX + tt*VT + lane];
            o.w = vsw[3*VPX + tt*VT + lane];
            size_t base = ((size_t)((n*8 + tt)*32 + lane))*16384
                        + (size_t)hout*128 + w0 + ph*4;
            *reinterpret_cast<float4*>(out + base) = o;
        }
        __syncwarp();
    }
}

extern "C" void kernel_launch(void* const* d_in, const int* in_sizes, int n_in,
                              void* d_out, int out_size)
{
    const float* x  = (const float*)d_in[0];
    const float* Wc = (const float*)d_in[1];
    const float* Wp = (const float*)d_in[2];
    const float* Wa = (const float*)d_in[3];
    const float* ba = (const float*)d_in[4];
    float* out = (float*)d_out;

    cudaFuncSetAttribute(caps2d_matwo_kernel,
                         cudaFuncAttributeMaxDynamicSharedMemorySize, SMEM_BYTES);

    dim3 grid(128/TW, 128/TH, 2);   // 16 x 32 x 2 = 1024 blocks
    caps2d_matwo_kernel<<<grid, 128, SMEM_BYTES>>>(x, Wc, Wp, Wa, ba, out);
}

// round 9
// speedup vs baseline: 1.3251x; 1.0005x over previous
#include <cuda_runtime.h>

// x: (2,4,32,128,128) f32; W_conv: (4,3,3,1,8); W_pos: (4,16,8);
// W_app: (4,16,8); b_app: (4,8). out: (2,8,32,128,128) f32.

#define TH 4
#define TW 8
#define RS 244
#define CS 1952
#define XS_FLOATS (4*CS)
#define MS_OFF   XS_FLOATS
#define MS_FLOATS (4*2*8*20)
#define BA_OFF   (MS_OFF + MS_FLOATS)
#define BA_FLOATS 32            // raw b_app [c][t]
#define VT 36
#define VPX (8*VT)
#define VWARP (4*VPX)
#define VS_OFF   (BA_OFF + BA_FLOATS)
#define SMEM_FLOATS (VS_OFF + 4*VWARP)
#define SMEM_BYTES  (SMEM_FLOATS*4)

typedef unsigned long long u64;

__device__ __forceinline__ void ffma2(u64& acc, u64 a, u64 b) {
    asm("fma.rn.f32x2 %0, %1, %2, %0;" : "+l"(acc) : "l"(a), "l"(b));
}
__device__ __forceinline__ u64 mul2(u64 a, u64 b) {
    u64 r; asm("mul.rn.f32x2 %0, %1, %2;" : "=l"(r) : "l"(a), "l"(b)); return r;
}
__device__ __forceinline__ u64 add2(u64 a, u64 b) {
    u64 r; asm("add.rn.f32x2 %0, %1, %2;" : "=l"(r) : "l"(a), "l"(b)); return r;
}
__device__ __forceinline__ u64 pack2(float x, float y) {
    u64 r; asm("mov.b64 %0, {%1, %2};" : "=l"(r) : "f"(x), "f"(y)); return r;
}
__device__ __forceinline__ float2 unpack2(u64 v) {
    float2 r; asm("mov.b64 {%0, %1}, %2;" : "=f"(r.x), "=f"(r.y) : "l"(v)); return r;
}

__global__ __launch_bounds__(128, 3)
void caps2d_matwo_kernel(const float* __restrict__ x,
                         const float* __restrict__ Wc,
                         const float* __restrict__ Wp,
                         const float* __restrict__ Wa,
                         const float* __restrict__ ba,
                         float* __restrict__ out)
{
    extern __shared__ float smem[];
    float* xs  = smem;
    float* MS  = smem + MS_OFF;
    float* baS = smem + BA_OFF;
    float* vs  = smem + VS_OFF;

    const int tid  = threadIdx.x;
    const int wid  = tid >> 5;
    const int lane = tid & 31;
    const int n    = blockIdx.z;
    const int w0   = blockIdx.x * TW;
    const int h0   = blockIdx.y * TH;

    // lane -> (q, t): q owns z in [8q, 8q+8); q<2 pos, q>=2 app
    const int q   = lane >> 3;
    const int t   = lane & 7;
    const int tb  = t & 1;
    const int ca  = t >> 1;
    const int qp  = q & 1;
    const int isApp = q >> 1;
    const int ch  = ca + isApp * 4;

    // ---- one-time per-block: normalized Mp, raw Ma, raw bias into shared ----
    if (tid < 32) {
        int c = tid >> 3, tt = tid & 7;
        float M[16];
#pragma unroll
        for (int i = 0; i < 16; i++) M[i] = Wp[c*128 + tt*16 + i];
#pragma unroll
        for (int k = 0; k < 4; k++) {
            float s = M[k]*M[k] + M[4+k]*M[4+k] + M[8+k]*M[8+k] + M[12+k]*M[12+k];
            float inv = rsqrtf(fmaxf(s, 1e-12f));
#pragma unroll
            for (int j = 0; j < 4; j++) M[j*4+k] *= inv;
        }
        float* mp = MS + ((c*2 + 0)*8 + tt)*20;
#pragma unroll
        for (int i = 0; i < 16; i++) mp[i] = M[i];
        float* mpa = MS + ((c*2 + 1)*8 + tt)*20;
#pragma unroll
        for (int i = 0; i < 16; i++) mpa[i] = Wa[c*128 + tt*16 + i];
        baS[c*8 + tt] = ba[c*8 + tt];
    }

    // ---- conv weights per lane ----
    float wk[36];
#pragma unroll
    for (int c = 0; c < 4; c++)
#pragma unroll
        for (int i = 0; i < 9; i++)
            wk[c*9 + i] = Wc[(c*9 + i)*8 + ch];

    // ---- tile load: x -> z-quad interleaved shared ----
    {
        const float* xin = x + (size_t)n * (128 * 16384);
        for (int idx = tid; idx < 1920; idx += 128) {
            int col = idx % 10;
            int tmp = idx / 10;
            int r   = tmp % 6;
            int pq  = tmp / 6;
            int gh  = h0 - 1 + r;
            int gw  = w0 - 1 + col;
            float4 v = make_float4(0.f, 0.f, 0.f, 0.f);
            if ((unsigned)gh < 128u && (unsigned)gw < 128u) {
                const float* gp = xin + (size_t)(pq*4)*16384 + gh*128 + gw;
                v.x = gp[0]; v.y = gp[16384]; v.z = gp[32768]; v.w = gp[49152];
            }
            *reinterpret_cast<float4*>(xs + (pq >> 3)*CS + (pq & 7)*RS + r*40 + col*4) = v;
        }
    }
    __syncthreads();

    // ---- hoist transform matrices + bias into registers (pixel-invariant) ----
    // Mr[c][j]: .x = (k0,k1) pair, .y = (k2,k3) pair of row j
    ulonglong2 Mr[4][4];
    u64 bias2[4];
#pragma unroll
    for (int c = 0; c < 4; c++) {
        const float* Mb = MS + ((c*2 + isApp)*8 + t)*20;
#pragma unroll
        for (int j = 0; j < 4; j++)
            Mr[c][j] = *reinterpret_cast<const ulonglong2*>(Mb + j*4);
        float bb = isApp ? baS[c*8 + t] : 0.f;
        bias2[c] = pack2(bb, bb);
    }

    const float cy = (float)(h0 + wid) * (1.0f/128.0f);
    const int   hout = h0 + wid;
    const float* xbase = xs + (4*tb + 2*qp)*RS + wid*40;
    float* vsw = vs + wid*VWARP;

    for (int ph = 0; ph < 2; ph++) {
#pragma unroll 1
        for (int pxl = 0; pxl < 4; pxl++) {
            const int px = ph*4 + pxl;
            const float cx = (float)(w0 + px) * (1.0f/128.0f);
            const u64 cxy = pack2(cx, cy);

            // ---- conv + transform (packed f32x2) ----
            u64 uh0[4], uh1[4], uh2[4], uh3[4];
#pragma unroll
            for (int c = 0; c < 4; c++) {
                u64 acc[4] = {0ull, 0ull, 0ull, 0ull};   // (z0,z1),(z2,z3) per kq
#pragma unroll
                for (int kq = 0; kq < 2; kq++) {
                    const float* bptr = xbase + c*CS + kq*RS + px*4;
#pragma unroll
                    for (int dy = 0; dy < 3; dy++)
#pragma unroll
                        for (int dx = 0; dx < 3; dx++) {
                            ulonglong2 xv = *reinterpret_cast<const ulonglong2*>(bptr + dy*40 + dx*4);
                            float w = wk[c*9 + dy*3 + dx];
                            u64 wp = pack2(w, w);
                            ffma2(acc[kq*2+0], xv.x, wp);
                            ffma2(acc[kq*2+1], xv.y, wp);
                        }
                }
                // bias pre-matmul (app lanes): (u + b) @ Ma  ==  u@Ma + b*colsum
                if (isApp) {
#pragma unroll
                    for (int j = 0; j < 4; j++) acc[j] = add2(acc[j], bias2[c]);
                }
                float2 t0 = unpack2(acc[0]), t1 = unpack2(acc[1]);
                float2 t2 = unpack2(acc[2]), t3 = unpack2(acc[3]);
                float u0 = t0.x, u1 = t0.y, u2 = t1.x, u3 = t1.y;
                float u4 = t2.x, u5 = t2.y, u6 = t3.x, u7 = t3.y;

                u64 a001 = 0ull, a023 = 0ull, a101 = 0ull, a123 = 0ull;
                u64 up;
                up = pack2(u0, u0); ffma2(a001, up, Mr[c][0].x); ffma2(a023, up, Mr[c][0].y);
                up = pack2(u1, u1); ffma2(a001, up, Mr[c][1].x); ffma2(a023, up, Mr[c][1].y);
                up = pack2(u2, u2); ffma2(a001, up, Mr[c][2].x); ffma2(a023, up, Mr[c][2].y);
                u64 u3p = pack2(u3, u3); ffma2(a001, u3p, Mr[c][3].x); ffma2(a023, u3p, Mr[c][3].y);
                up = pack2(u4, u4); ffma2(a101, up, Mr[c][0].x); ffma2(a123, up, Mr[c][0].y);
                up = pack2(u5, u5); ffma2(a101, up, Mr[c][1].x); ffma2(a123, up, Mr[c][1].y);
                up = pack2(u6, u6); ffma2(a101, up, Mr[c][2].x); ffma2(a123, up, Mr[c][2].y);
                u64 u7p = pack2(u7, u7); ffma2(a101, u7p, Mr[c][3].x); ffma2(a123, u7p, Mr[c][3].y);
                if (!isApp) {   // coord addend: (k0 += u3*cx, k1 += u3*cy)
                    ffma2(a001, u3p, cxy);
                    ffma2(a101, u7p, cxy);
                }
                u64* dst = (c==0)?uh0:(c==1)?uh1:(c==2)?uh2:uh3;
                dst[0]=a001; dst[1]=a023; dst[2]=a101; dst[3]=a123;
            }

            // ---- routing: lane-local p, combined-kind butterflies ----
            float b0=0.f, b1=0.f, b2=0.f, b3=0.f;
            u64 pzp[4];
            float pz[8];
            float invpos = 0.f, fapp = 0.f;
#pragma unroll
            for (int it = 0; it < 3; it++) {
                float r0 = __fdividef(1.f, 1.f + __expf(-b0));
                float r1 = __fdividef(1.f, 1.f + __expf(-b1));
                float r2 = __fdividef(1.f, 1.f + __expf(-b2));
                float r3 = __fdividef(1.f, 1.f + __expf(-b3));
                u64 rp0 = pack2(r0,r0), rp1 = pack2(r1,r1);
                u64 rp2 = pack2(r2,r2), rp3 = pack2(r3,r3);
#pragma unroll
                for (int j = 0; j < 4; j++) {
                    u64 p = 0ull;
                    ffma2(p, uh0[j], rp0); ffma2(p, uh1[j], rp1);
                    ffma2(p, uh2[j], rp2); ffma2(p, uh3[j], rp3);
                    pzp[j] = p;
                }
#pragma unroll
                for (int j = 0; j < 4; j++) {
                    float2 f = unpack2(pzp[j]);
                    pz[j*2+0] = f.x; pz[j*2+1] = f.y;
                }
                // own-kind partial: pos lanes -> max|p|, app lanes -> sum p^2
                float v;
                if (!isApp) {
                    v = 0.f;
#pragma unroll
                    for (int z = 0; z < 8; z++) v = fmaxf(v, fabsf(pz[z]));
                } else {
                    v = 0.f;
#pragma unroll
                    for (int z = 0; z < 8; z++) v = fmaf(pz[z], pz[z], v);
                }
                float o8 = __shfl_xor_sync(0xffffffffu, v, 8);
                v = isApp ? (v + o8) : fmaxf(v, o8);              // full own-kind
                float o16 = __shfl_xor_sync(0xffffffffu, v, 16);  // other kind full
                float mmF = isApp ? o16 : v;
                float sqF = isApp ? v : o16;
                invpos = __fdividef(1.f, mmF);
                fapp   = __fdividef(sqF, 1.f + sqF) * rsqrtf(sqF + 1e-9f);
                if (it < 2) {
#pragma unroll
                    for (int c = 0; c < 4; c++) {
                        const u64* uc = (c==0)?uh0:(c==1)?uh1:(c==2)?uh2:uh3;
                        u64 d = 0ull;
                        ffma2(d, uc[0], pzp[0]); ffma2(d, uc[1], pzp[1]);
                        ffma2(d, uc[2], pzp[2]); ffma2(d, uc[3], pzp[3]);
                        float2 dd = unpack2(d);
                        float s = dd.x + dd.y;                       // own-kind partial
                        s += __shfl_xor_sync(0xffffffffu, s, 8);     // full own-kind
                        float o = __shfl_xor_sync(0xffffffffu, s, 16); // other kind
                        float dp = isApp ? o : s;
                        float da = isApp ? s : o;
                        float rt = (dp * invpos) * (da * fapp);
                        if (c==0) b0 += rt; else if (c==1) b1 += rt;
                        else if (c==2) b2 += rt; else b3 += rt;
                    }
                }
            }
            // stage scaled v for own 8 z (packed mul + 16B stores)
            float sc = isApp ? fapp : invpos;
            u64 scp = pack2(sc, sc);
            float* vp = vsw + pxl*VPX + t*VT + q*8;
            ulonglong2 s0, s1;
            s0.x = mul2(pzp[0], scp); s0.y = mul2(pzp[1], scp);
            s1.x = mul2(pzp[2], scp); s1.y = mul2(pzp[3], scp);
            *reinterpret_cast<ulonglong2*>(vp)     = s0;
            *reinterpret_cast<ulonglong2*>(vp + 4) = s1;
        }

        __syncwarp();
        // ---- flush 4 columns: lane = z, float4 along w ----
#pragma unroll
        for (int tt = 0; tt < 8; tt++) {
            float4 o;
            o.x = vsw[0*VPX + tt*VT + lane];
            o.y = vsw[1*VPX + tt*VT + lane];
            o.z = vsw[2*VPX + tt*VT + lane];
            o.w = vsw[3*VPX + tt*VT + lane];
            size_t base = ((size_t)((n*8 + tt)*32 + lane))*16384
                        + (size_t)hout*128 + w0 + ph*4;
            *reinterpret_cast<float4*>(out + base) = o;
        }
        __syncwarp();
    }
}

extern "C" void kernel_launch(void* const* d_in, const int* in_sizes, int n_in,
                              void* d_out, int out_size)
{
    const float* x  = (const float*)d_in[0];
    const float* Wc = (const float*)d_in[1];
    const float* Wp = (const float*)d_in[2];
    const float* Wa = (const float*)d_in[3];
    const float* ba = (const float*)d_in[4];
    float* out = (float*)d_out;

    cudaFuncSetAttribute(caps2d_matwo_kernel,
                         cudaFuncAttributeMaxDynamicSharedMemorySize, SMEM_BYTES);

    dim3 grid(128/TW, 128/TH, 2);   // 16 x 32 x 2 = 1024 blocks
    caps2d_matwo_kernel<<<grid, 128, SMEM_BYTES>>>(x, Wc, Wp, Wa, ba, out);
}

// round 10
// speedup vs baseline: 1.4189x; 1.0708x over previous
#include <cuda_runtime.h>

// x: (2,4,32,128,128) f32; W_conv: (4,3,3,1,8); W_pos: (4,16,8);
// W_app: (4,16,8); b_app: (4,8). out: (2,8,32,128,128) f32.

#define TH 4
#define TW 8
#define RS 244
#define CS 1952
#define XS_FLOATS (4*CS)
#define MS_OFF   XS_FLOATS
#define MS_FLOATS (4*2*8*20)
#define BA_OFF   (MS_OFF + MS_FLOATS)
#define BA_FLOATS 32
#define VT 36
#define VPX (8*VT)
#define VWARP (4*VPX)
#define VS_OFF   (BA_OFF + BA_FLOATS)
#define SMEM_FLOATS (VS_OFF + 4*VWARP)
#define SMEM_BYTES  (SMEM_FLOATS*4)

typedef unsigned long long u64;

__device__ __forceinline__ void ffma2(u64& acc, u64 a, u64 b) {
    asm("fma.rn.f32x2 %0, %1, %2, %0;" : "+l"(acc) : "l"(a), "l"(b));
}
__device__ __forceinline__ u64 mul2(u64 a, u64 b) {
    u64 r; asm("mul.rn.f32x2 %0, %1, %2;" : "=l"(r) : "l"(a), "l"(b)); return r;
}
__device__ __forceinline__ u64 add2(u64 a, u64 b) {
    u64 r; asm("add.rn.f32x2 %0, %1, %2;" : "=l"(r) : "l"(a), "l"(b)); return r;
}
__device__ __forceinline__ u64 pack2(float x, float y) {
    u64 r; asm("mov.b64 %0, {%1, %2};" : "=l"(r) : "f"(x), "f"(y)); return r;
}
__device__ __forceinline__ float2 unpack2(u64 v) {
    float2 r; asm("mov.b64 {%0, %1}, %2;" : "=f"(r.x), "=f"(r.y) : "l"(v)); return r;
}
__device__ __forceinline__ float sigm(float b) {
    return __fdividef(1.f, 1.f + __expf(-b));
}

__global__ __launch_bounds__(128, 3)
void caps2d_matwo_kernel(const float* __restrict__ x,
                         const float* __restrict__ Wc,
                         const float* __restrict__ Wp,
                         const float* __restrict__ Wa,
                         const float* __restrict__ ba,
                         float* __restrict__ out)
{
    extern __shared__ float smem[];
    float* xs  = smem;
    float* MS  = smem + MS_OFF;
    float* baS = smem + BA_OFF;
    float* vs  = smem + VS_OFF;

    const int tid  = threadIdx.x;
    const int wid  = tid >> 5;
    const int lane = tid & 31;
    const int n    = blockIdx.z;
    const int w0   = blockIdx.x * TW;
    const int h0   = blockIdx.y * TH;

    const int q   = lane >> 3;
    const int t   = lane & 7;
    const int tb  = t & 1;
    const int ca  = t >> 1;
    const int qp  = q & 1;
    const int isApp = q >> 1;
    const int ch  = ca + isApp * 4;

    // ---- one-time: normalized Mp, raw Ma, raw bias into shared ----
    if (tid < 32) {
        int c = tid >> 3, tt = tid & 7;
        float M[16];
#pragma unroll
        for (int i = 0; i < 16; i++) M[i] = Wp[c*128 + tt*16 + i];
#pragma unroll
        for (int k = 0; k < 4; k++) {
            float s = M[k]*M[k] + M[4+k]*M[4+k] + M[8+k]*M[8+k] + M[12+k]*M[12+k];
            float inv = rsqrtf(fmaxf(s, 1e-12f));
#pragma unroll
            for (int j = 0; j < 4; j++) M[j*4+k] *= inv;
        }
        float* mp = MS + ((c*2 + 0)*8 + tt)*20;
#pragma unroll
        for (int i = 0; i < 16; i++) mp[i] = M[i];
        float* mpa = MS + ((c*2 + 1)*8 + tt)*20;
#pragma unroll
        for (int i = 0; i < 16; i++) mpa[i] = Wa[c*128 + tt*16 + i];
        baS[c*8 + tt] = ba[c*8 + tt];
    }

    // ---- conv weights per lane ----
    float wk[36];
#pragma unroll
    for (int c = 0; c < 4; c++)
#pragma unroll
        for (int i = 0; i < 9; i++)
            wk[c*9 + i] = Wc[(c*9 + i)*8 + ch];

    // ---- tile load: x -> z-quad interleaved shared ----
    {
        const float* xin = x + (size_t)n * (128 * 16384);
        for (int idx = tid; idx < 1920; idx += 128) {
            int col = idx % 10;
            int tmp = idx / 10;
            int r   = tmp % 6;
            int pq  = tmp / 6;
            int gh  = h0 - 1 + r;
            int gw  = w0 - 1 + col;
            float4 v = make_float4(0.f, 0.f, 0.f, 0.f);
            if ((unsigned)gh < 128u && (unsigned)gw < 128u) {
                const float* gp = xin + (size_t)(pq*4)*16384 + gh*128 + gw;
                v.x = gp[0]; v.y = gp[16384]; v.z = gp[32768]; v.w = gp[49152];
            }
            *reinterpret_cast<float4*>(xs + (pq >> 3)*CS + (pq & 7)*RS + r*40 + col*4) = v;
        }
    }
    __syncthreads();

    const float cy = (float)(h0 + wid) * (1.0f/128.0f);
    const int   hout = h0 + wid;
    const float* xbase = xs + (4*tb + 2*qp)*RS + wid*40;
    float* vsw = vs + wid*VWARP;
    const u64 half2 = pack2(0.5f, 0.5f);

#pragma unroll 1
    for (int ph = 0; ph < 2; ph++) {
#pragma unroll 1
        for (int pp = 0; pp < 2; pp++) {
            const int pxa = ph*4 + pp*2;
            const u64 cxyA = pack2((float)(w0 + pxa)     * (1.0f/128.0f), cy);
            const u64 cxyB = pack2((float)(w0 + pxa + 1) * (1.0f/128.0f), cy);

            // ---- conv + transform for px pair (shared taps) ----
            u64 uhA[16], uhB[16];           // [c*4 + j]
            u64 SA[4] = {0,0,0,0}, SB[4] = {0,0,0,0};
#pragma unroll
            for (int c = 0; c < 4; c++) {
                u64 aA[4] = {0,0,0,0}, aB[4] = {0,0,0,0};
#pragma unroll
                for (int kq = 0; kq < 2; kq++) {
                    const float* bp = xbase + c*CS + kq*RS + pxa*4;
#pragma unroll
                    for (int dy = 0; dy < 3; dy++) {
                        const float* rp = bp + dy*40;
                        ulonglong2 v0 = *reinterpret_cast<const ulonglong2*>(rp);
                        ulonglong2 v1 = *reinterpret_cast<const ulonglong2*>(rp + 4);
                        ulonglong2 v2 = *reinterpret_cast<const ulonglong2*>(rp + 8);
                        ulonglong2 v3 = *reinterpret_cast<const ulonglong2*>(rp + 12);
                        float w0f = wk[c*9 + dy*3 + 0];
                        float w1f = wk[c*9 + dy*3 + 1];
                        float w2f = wk[c*9 + dy*3 + 2];
                        u64 w0p = pack2(w0f, w0f);
                        u64 w1p = pack2(w1f, w1f);
                        u64 w2p = pack2(w2f, w2f);
                        ffma2(aA[kq*2+0], v0.x, w0p); ffma2(aA[kq*2+1], v0.y, w0p);
                        ffma2(aB[kq*2+0], v1.x, w0p); ffma2(aB[kq*2+1], v1.y, w0p);
                        ffma2(aA[kq*2+0], v1.x, w1p); ffma2(aA[kq*2+1], v1.y, w1p);
                        ffma2(aB[kq*2+0], v2.x, w1p); ffma2(aB[kq*2+1], v2.y, w1p);
                        ffma2(aA[kq*2+0], v2.x, w2p); ffma2(aA[kq*2+1], v2.y, w2p);
                        ffma2(aB[kq*2+0], v3.x, w2p); ffma2(aB[kq*2+1], v3.y, w2p);
                    }
                }
                // bias pre-matmul (app lanes): (u+b)@Ma == u@Ma + b*colsum
                if (isApp) {
                    float bb = baS[c*8 + t];
                    u64 b2 = pack2(bb, bb);
#pragma unroll
                    for (int j = 0; j < 4; j++) {
                        aA[j] = add2(aA[j], b2);
                        aB[j] = add2(aB[j], b2);
                    }
                }
                const float* Mb = MS + ((c*2 + isApp)*8 + t)*20;
                ulonglong2 M0 = *reinterpret_cast<const ulonglong2*>(Mb);
                ulonglong2 M1 = *reinterpret_cast<const ulonglong2*>(Mb + 4);
                ulonglong2 M2 = *reinterpret_cast<const ulonglong2*>(Mb + 8);
                ulonglong2 M3 = *reinterpret_cast<const ulonglong2*>(Mb + 12);

                // transform A
                {
                    float2 t0 = unpack2(aA[0]), t1 = unpack2(aA[1]);
                    float2 t2 = unpack2(aA[2]), t3 = unpack2(aA[3]);
                    u64 r01 = 0ull, r23 = 0ull, s01 = 0ull, s23 = 0ull;
                    u64 up;
                    up = pack2(t0.x, t0.x); ffma2(r01, up, M0.x); ffma2(r23, up, M0.y);
                    up = pack2(t0.y, t0.y); ffma2(r01, up, M1.x); ffma2(r23, up, M1.y);
                    up = pack2(t1.x, t1.x); ffma2(r01, up, M2.x); ffma2(r23, up, M2.y);
                    u64 u3p = pack2(t1.y, t1.y); ffma2(r01, u3p, M3.x); ffma2(r23, u3p, M3.y);
                    up = pack2(t2.x, t2.x); ffma2(s01, up, M0.x); ffma2(s23, up, M0.y);
                    up = pack2(t2.y, t2.y); ffma2(s01, up, M1.x); ffma2(s23, up, M1.y);
                    up = pack2(t3.x, t3.x); ffma2(s01, up, M2.x); ffma2(s23, up, M2.y);
                    u64 u7p = pack2(t3.y, t3.y); ffma2(s01, u7p, M3.x); ffma2(s23, u7p, M3.y);
                    if (!isApp) { ffma2(r01, u3p, cxyA); ffma2(s01, u7p, cxyA); }
                    uhA[c*4+0] = r01; uhA[c*4+1] = r23; uhA[c*4+2] = s01; uhA[c*4+3] = s23;
                    SA[0] = add2(SA[0], r01); SA[1] = add2(SA[1], r23);
                    SA[2] = add2(SA[2], s01); SA[3] = add2(SA[3], s23);
                }
                // transform B
                {
                    float2 t0 = unpack2(aB[0]), t1 = unpack2(aB[1]);
                    float2 t2 = unpack2(aB[2]), t3 = unpack2(aB[3]);
                    u64 r01 = 0ull, r23 = 0ull, s01 = 0ull, s23 = 0ull;
                    u64 up;
                    up = pack2(t0.x, t0.x); ffma2(r01, up, M0.x); ffma2(r23, up, M0.y);
                    up = pack2(t0.y, t0.y); ffma2(r01, up, M1.x); ffma2(r23, up, M1.y);
                    up = pack2(t1.x, t1.x); ffma2(r01, up, M2.x); ffma2(r23, up, M2.y);
                    u64 u3p = pack2(t1.y, t1.y); ffma2(r01, u3p, M3.x); ffma2(r23, u3p, M3.y);
                    up = pack2(t2.x, t2.x); ffma2(s01, up, M0.x); ffma2(s23, up, M0.y);
                    up = pack2(t2.y, t2.y); ffma2(s01, up, M1.x); ffma2(s23, up, M1.y);
                    up = pack2(t3.x, t3.x); ffma2(s01, up, M2.x); ffma2(s23, up, M2.y);
                    u64 u7p = pack2(t3.y, t3.y); ffma2(s01, u7p, M3.x); ffma2(s23, u7p, M3.y);
                    if (!isApp) { ffma2(r01, u3p, cxyB); ffma2(s01, u7p, cxyB); }
                    uhB[c*4+0] = r01; uhB[c*4+1] = r23; uhB[c*4+2] = s01; uhB[c*4+3] = s23;
                    SB[0] = add2(SB[0], r01); SB[1] = add2(SB[1], r23);
                    SB[2] = add2(SB[2], s01); SB[3] = add2(SB[3], s23);
                }
            }

            // ---- routing: two interleaved chains (A, B) ----
            float bA0=0.f,bA1=0.f,bA2=0.f,bA3=0.f;
            float bB0=0.f,bB1=0.f,bB2=0.f,bB3=0.f;
            u64 pA[4], pB[4];
            float invA=0.f, faA=0.f, invB=0.f, faB=0.f;
#pragma unroll
            for (int it = 0; it < 3; it++) {
                if (it == 0) {
                    // sigmoid(0)=0.5 exactly; x0.5 exact: p = 0.5 * sum_c uh
#pragma unroll
                    for (int j = 0; j < 4; j++) {
                        pA[j] = mul2(SA[j], half2);
                        pB[j] = mul2(SB[j], half2);
                    }
                } else {
                    u64 rA0p = pack2(sigm(bA0), sigm(bA0));
                    u64 rA1p = pack2(sigm(bA1), sigm(bA1));
                    u64 rA2p = pack2(sigm(bA2), sigm(bA2));
                    u64 rA3p = pack2(sigm(bA3), sigm(bA3));
                    u64 rB0p = pack2(sigm(bB0), sigm(bB0));
                    u64 rB1p = pack2(sigm(bB1), sigm(bB1));
                    u64 rB2p = pack2(sigm(bB2), sigm(bB2));
                    u64 rB3p = pack2(sigm(bB3), sigm(bB3));
#pragma unroll
                    for (int j = 0; j < 4; j++) {
                        u64 p = 0ull;
                        ffma2(p, uhA[j],    rA0p); ffma2(p, uhA[4+j],  rA1p);
                        ffma2(p, uhA[8+j],  rA2p); ffma2(p, uhA[12+j], rA3p);
                        pA[j] = p;
                        u64 pb = 0ull;
                        ffma2(pb, uhB[j],    rB0p); ffma2(pb, uhB[4+j],  rB1p);
                        ffma2(pb, uhB[8+j],  rB2p); ffma2(pb, uhB[12+j], rB3p);
                        pB[j] = pb;
                    }
                }
                // own-kind partials (pos: tree max|p|; app: packed sum p^2)
                float vA, vB;
                if (!isApp) {
                    float2 f0 = unpack2(pA[0]), f1 = unpack2(pA[1]);
                    float2 f2 = unpack2(pA[2]), f3 = unpack2(pA[3]);
                    float m0 = fmaxf(fabsf(f0.x), fabsf(f0.y));
                    float m1 = fmaxf(fabsf(f1.x), fabsf(f1.y));
                    float m2 = fmaxf(fabsf(f2.x), fabsf(f2.y));
                    float m3 = fmaxf(fabsf(f3.x), fabsf(f3.y));
                    vA = fmaxf(fmaxf(m0, m1), fmaxf(m2, m3));
                    f0 = unpack2(pB[0]); f1 = unpack2(pB[1]);
                    f2 = unpack2(pB[2]); f3 = unpack2(pB[3]);
                    m0 = fmaxf(fabsf(f0.x), fabsf(f0.y));
                    m1 = fmaxf(fabsf(f1.x), fabsf(f1.y));
                    m2 = fmaxf(fabsf(f2.x), fabsf(f2.y));
                    m3 = fmaxf(fabsf(f3.x), fabsf(f3.y));
                    vB = fmaxf(fmaxf(m0, m1), fmaxf(m2, m3));
                } else {
                    u64 s2 = 0ull;
                    ffma2(s2, pA[0], pA[0]); ffma2(s2, pA[1], pA[1]);
                    ffma2(s2, pA[2], pA[2]); ffma2(s2, pA[3], pA[3]);
                    float2 dd = unpack2(s2);
                    vA = dd.x + dd.y;
                    u64 s2b = 0ull;
                    ffma2(s2b, pB[0], pB[0]); ffma2(s2b, pB[1], pB[1]);
                    ffma2(s2b, pB[2], pB[2]); ffma2(s2b, pB[3], pB[3]);
                    float2 db = unpack2(s2b);
                    vB = db.x + db.y;
                }
                float o8A = __shfl_xor_sync(0xffffffffu, vA, 8);
                float o8B = __shfl_xor_sync(0xffffffffu, vB, 8);
                vA = isApp ? (vA + o8A) : fmaxf(vA, o8A);
                vB = isApp ? (vB + o8B) : fmaxf(vB, o8B);
                float o16A = __shfl_xor_sync(0xffffffffu, vA, 16);
                float o16B = __shfl_xor_sync(0xffffffffu, vB, 16);
                float mmA = isApp ? o16A : vA, sqA = isApp ? vA : o16A;
                float mmB = isApp ? o16B : vB, sqB = isApp ? vB : o16B;
                invA = __fdividef(1.f, mmA);
                faA  = __fdividef(sqA, 1.f + sqA) * rsqrtf(sqA + 1e-9f);
                invB = __fdividef(1.f, mmB);
                faB  = __fdividef(sqB, 1.f + sqB) * rsqrtf(sqB + 1e-9f);
                if (it < 2) {
#pragma unroll
                    for (int c = 0; c < 4; c++) {
                        u64 dA = 0ull, dB = 0ull;
                        ffma2(dA, uhA[c*4+0], pA[0]); ffma2(dA, uhA[c*4+1], pA[1]);
                        ffma2(dA, uhA[c*4+2], pA[2]); ffma2(dA, uhA[c*4+3], pA[3]);
                        ffma2(dB, uhB[c*4+0], pB[0]); ffma2(dB, uhB[c*4+1], pB[1]);
                        ffma2(dB, uhB[c*4+2], pB[2]); ffma2(dB, uhB[c*4+3], pB[3]);
                        float2 ddA = unpack2(dA), ddB = unpack2(dB);
                        float sA = ddA.x + ddA.y, sB = ddB.x + ddB.y;
                        sA += __shfl_xor_sync(0xffffffffu, sA, 8);
                        sB += __shfl_xor_sync(0xffffffffu, sB, 8);
                        float oA = __shfl_xor_sync(0xffffffffu, sA, 16);
                        float oB = __shfl_xor_sync(0xffffffffu, sB, 16);
                        float dpA = isApp ? oA : sA, daA = isApp ? sA : oA;
                        float dpB = isApp ? oB : sB, daB = isApp ? sB : oB;
                        float rtA = (dpA * invA) * (daA * faA);
                        float rtB = (dpB * invB) * (daB * faB);
                        if (c==0) { bA0 += rtA; bB0 += rtB; }
                        else if (c==1) { bA1 += rtA; bB1 += rtB; }
                        else if (c==2) { bA2 += rtA; bB2 += rtB; }
                        else { bA3 += rtA; bB3 += rtB; }
                    }
                }
            }
            // stage scaled v for both pixels
            {
                float scA = isApp ? faA : invA;
                float scB = isApp ? faB : invB;
                u64 sAp = pack2(scA, scA), sBp = pack2(scB, scB);
                float* vpA = vsw + (pp*2)*VPX + t*VT + q*8;
                float* vpB = vpA + VPX;
                ulonglong2 w0v, w1v;
                w0v.x = mul2(pA[0], sAp); w0v.y = mul2(pA[1], sAp);
                w1v.x = mul2(pA[2], sAp); w1v.y = mul2(pA[3], sAp);
                *reinterpret_cast<ulonglong2*>(vpA)     = w0v;
                *reinterpret_cast<ulonglong2*>(vpA + 4) = w1v;
                w0v.x = mul2(pB[0], sBp); w0v.y = mul2(pB[1], sBp);
                w1v.x = mul2(pB[2], sBp); w1v.y = mul2(pB[3], sBp);
                *reinterpret_cast<ulonglong2*>(vpB)     = w0v;
                *reinterpret_cast<ulonglong2*>(vpB + 4) = w1v;
            }
        }

        __syncwarp();
        // ---- flush 4 columns: lane = z, float4 along w ----
#pragma unroll
        for (int tt = 0; tt < 8; tt++) {
            float4 o;
            o.x = vsw[0*VPX + tt*VT + lane];
            o.y = vsw[1*VPX + tt*VT + lane];
            o.z = vsw[2*VPX + tt*VT + lane];
            o.w = vsw[3*VPX + tt*VT + lane];
            size_t base = ((size_t)((n*8 + tt)*32 + lane))*16384
                        + (size_t)hout*128 + w0 + ph*4;
            *reinterpret_cast<float4*>(out + base) = o;
        }
        __syncwarp();
    }
}

extern "C" void kernel_launch(void* const* d_in, const int* in_sizes, int n_in,
                              void* d_out, int out_size)
{
    const float* x  = (const float*)d_in[0];
    const float* Wc = (const float*)d_in[1];
    const float* Wp = (const float*)d_in[2];
    const float* Wa = (const float*)d_in[3];
    const float* ba = (const float*)d_in[4];
    float* out = (float*)d_out;

    cudaFuncSetAttribute(caps2d_matwo_kernel,
                         cudaFuncAttributeMaxDynamicSharedMemorySize, SMEM_BYTES);

    dim3 grid(128/TW, 128/TH, 2);   // 16 x 32 x 2 = 1024 blocks
    caps2d_matwo_kernel<<<grid, 128, SMEM_BYTES>>>(x, Wc, Wp, Wa, ba, out);
}